// round 10
// baseline (speedup 1.0000x reference)
#include <cuda_runtime.h>
#include <math.h>

#define NN 100000
#define EE 1600000
#define NN3 (3 * NN)
#define EE3 (3 * EE)
#define SCAN_BS 1024
#define SCAN_NB ((NN3 + SCAN_BS - 1) / SCAN_BS)   // 293

// ---------------- scratch (static device globals; no allocation) ------------
// NOTE: device globals are zero-initialized; lin_kernel only writes cols 0..49,
// so pad cols 50..63 of g_xl/g_xr stay 0 forever (aggregate relies on this).
__device__ __align__(16) float g_xl[(size_t)3 * NN * 64];   // row stride 64
__device__ __align__(16) float g_xr[(size_t)3 * NN * 64];
__device__ __align__(16) float g_h[(size_t)NN * 150];
__device__ __align__(16) float g_p[(size_t)NN * 160];
__device__ __align__(16) float g_q[(size_t)NN * 80];
__device__ int   g_rowptr[NN3 + 1];
__device__ int   g_cursor[NN3];
__device__ int   g_csr[EE3];
__device__ int   g_bsums[SCAN_BS];

// Resolve scratch buffers INSIDE device code (host-side __device__ symbol
// arguments are the round-3/4 bug — never pass g_* from kernel_launch).
__device__ __forceinline__ float* sel_buf(int s) {
    return (s == 0) ? g_h : ((s == 1) ? g_p : g_q);
}

// ---------------- CSR build (fused over 3 relations, round-7 verbatim) ------
__global__ void zero_cursor_kernel() {
    int i = blockIdx.x * blockDim.x + threadIdx.x;
    if (i < NN3) g_cursor[i] = 0;
}

__global__ void hist_kernel(const int* __restrict__ d0, const int* __restrict__ d1,
                            const int* __restrict__ d2) {
    for (int e = blockIdx.x * blockDim.x + threadIdx.x; e < EE;
         e += gridDim.x * blockDim.x) {
        atomicAdd(&g_cursor[__ldg(&d0[e])], 1);
        atomicAdd(&g_cursor[NN + __ldg(&d1[e])], 1);
        atomicAdd(&g_cursor[2 * NN + __ldg(&d2[e])], 1);
    }
}

__global__ void scan1_kernel() {
    __shared__ int sh[SCAN_BS];
    int tid = threadIdx.x;
    int i = blockIdx.x * SCAN_BS + tid;
    int v = (i < NN3) ? g_cursor[i] : 0;
    sh[tid] = v;
    __syncthreads();
    for (int off = 1; off < SCAN_BS; off <<= 1) {
        int t = (tid >= off) ? sh[tid - off] : 0;
        __syncthreads();
        sh[tid] += t;
        __syncthreads();
    }
    if (i < NN3) g_rowptr[i] = sh[tid] - v;
    if (tid == SCAN_BS - 1) g_bsums[blockIdx.x] = sh[tid];
}

__global__ void scan2_kernel() {
    __shared__ int sh[SCAN_BS];
    int tid = threadIdx.x;
    int v = (tid < SCAN_NB) ? g_bsums[tid] : 0;
    sh[tid] = v;
    __syncthreads();
    for (int off = 1; off < SCAN_BS; off <<= 1) {
        int t = (tid >= off) ? sh[tid - off] : 0;
        __syncthreads();
        sh[tid] += t;
        __syncthreads();
    }
    if (tid < SCAN_NB) g_bsums[tid] = sh[tid] - v;
}

__global__ void scan3_kernel() {
    int i = blockIdx.x * SCAN_BS + threadIdx.x;
    if (i < NN3) {
        int r = g_rowptr[i] + g_bsums[blockIdx.x];
        g_rowptr[i] = r;
        g_cursor[i] = r;
    }
    if (blockIdx.x == 0 && threadIdx.x == 0) g_rowptr[NN3] = EE3;
}

__global__ void scatter_kernel(const int* __restrict__ s0, const int* __restrict__ d0,
                               const int* __restrict__ s1, const int* __restrict__ d1,
                               const int* __restrict__ s2, const int* __restrict__ d2) {
    for (int e = blockIdx.x * blockDim.x + threadIdx.x; e < EE;
         e += gridDim.x * blockDim.x) {
        int p0 = atomicAdd(&g_cursor[__ldg(&d0[e])], 1);
        g_csr[p0] = __ldg(&s0[e]);
        int p1 = atomicAdd(&g_cursor[NN + __ldg(&d1[e])], 1);
        g_csr[p1] = __ldg(&s1[e]);
        int p2 = atomicAdd(&g_cursor[2 * NN + __ldg(&d2[e])], 1);
        g_csr[p2] = __ldg(&s2[e]);
    }
}

// ---------------- fused linear transforms (round-7 verbatim) ----------------
struct LinParams {
    const float* Wl[3]; const float* bl[3];
    const float* Wr[3]; const float* br[3];
};

__global__ __launch_bounds__(256) void lin_kernel(const float* __restrict__ x, LinParams P) {
    __shared__ __align__(16) float sW[6][25 * 50];   // l0..l2, r0..r2
    __shared__ float sB[6][64];
    __shared__ float sX[32][26];
    int tid = threadIdx.x;

    for (int i = tid; i < 25 * 50; i += 256) {
#pragma unroll
        for (int t = 0; t < 3; t++) {
            sW[t][i]     = __ldg(&P.Wl[t][i]);
            sW[3 + t][i] = __ldg(&P.Wr[t][i]);
        }
    }
    if (tid < 50) {
#pragma unroll
        for (int t = 0; t < 3; t++) {
            sB[t][tid]     = __ldg(&P.bl[t][tid]);
            sB[3 + t][tid] = __ldg(&P.br[t][tid]);
        }
    }
    int node0 = blockIdx.x * 32;
    for (int i = tid; i < 32 * 25; i += 256) {
        int nl = i / 25, k = i - nl * 25;
        int n = node0 + nl;
        sX[nl][k] = (n < NN) ? __ldg(&x[(size_t)n * 25 + k]) : 0.f;
    }
    __syncthreads();

#pragma unroll
    for (int s = 0; s < 8; ++s) {
        int slot = s * 256 + tid;           // 0..2047 = 32 nodes x 64 cols
        int nl = slot >> 6, c = slot & 63;
        if (c >= 50) continue;
        int n = node0 + nl;
        if (n >= NN) continue;
        float al0 = sB[0][c], al1 = sB[1][c], al2 = sB[2][c];
        float ar0 = sB[3][c], ar1 = sB[4][c], ar2 = sB[5][c];
#pragma unroll
        for (int k = 0; k < 25; k++) {
            float xv = sX[nl][k];
            al0 += xv * sW[0][k * 50 + c];
            al1 += xv * sW[1][k * 50 + c];
            al2 += xv * sW[2][k * 50 + c];
            ar0 += xv * sW[3][k * 50 + c];
            ar1 += xv * sW[4][k * 50 + c];
            ar2 += xv * sW[5][k * 50 + c];
        }
        size_t o = (size_t)n * 64 + c;
        const size_t R = (size_t)NN * 64;
        g_xl[o] = al0;         g_xr[o] = ar0;
        g_xl[R + o] = al1;     g_xr[R + o] = ar1;
        g_xl[2 * R + o] = al2; g_xr[2 * R + o] = ar2;
    }
}

// ---------------- GATv2 aggregate: float2 lanes, one warp per (rel, node) ----
// Lane c in [0,25) owns dims {2c, 2c+1} as one float2 -> one LDG.64 per edge row.
// Lanes 25..31 load the zero pad (cols 50..63) and carry att2 = 0, so they are
// branchless no-ops in the reduction.
struct AttParams { const float* att[3]; const float* bo[3]; };

__device__ __forceinline__ float2 leaky2(float2 z) {
    float2 r;
    r.x = fmaxf(z.x, 0.2f * z.x);
    r.y = fmaxf(z.y, 0.2f * z.y);
    return r;
}

__global__ __launch_bounds__(256) void aggregate_kernel(AttParams P) {
    int warp = (blockIdx.x * blockDim.x + threadIdx.x) >> 5;
    if (warp >= NN3) return;
    int lane = threadIdx.x & 31;
    int t = warp / NN;
    int i = warp - t * NN;
    bool act = (lane < 25);

    const float2* xlb = (const float2*)(g_xl + (size_t)t * NN * 64);  // row = 32 float2
    const float2* xrb = (const float2*)(g_xr + (size_t)t * NN * 64);

    float2 xr2 = xrb[(size_t)i * 32 + lane];   // pad lanes read zeros
    float2 xl2 = xlb[(size_t)i * 32 + lane];
    float2 a2;
    a2.x = act ? __ldg(&P.att[t][2 * lane]) : 0.f;
    a2.y = act ? __ldg(&P.att[t][2 * lane + 1]) : 0.f;

    // self loop
    {
        float2 m = leaky2(make_float2(xl2.x + xr2.x, xl2.y + xr2.y));
        float p = m.x * a2.x + m.y * a2.y;
#pragma unroll
        for (int o = 16; o; o >>= 1) p += __shfl_xor_sync(0xFFFFFFFFu, p, o);
        float w = __expf(p);
        // fallthrough init below uses w
        float denom = w;
        float2 acc = make_float2(w * xl2.x, w * xl2.y);

        int beg = g_rowptr[t * NN + i];
        int end = g_rowptr[t * NN + i + 1];
        int e = beg;
        for (; e + 4 <= end; e += 4) {
            int j0 = __ldg(&g_csr[e]);
            int j1 = __ldg(&g_csr[e + 1]);
            int j2 = __ldg(&g_csr[e + 2]);
            int j3 = __ldg(&g_csr[e + 3]);
            float2 y0 = xlb[(size_t)j0 * 32 + lane];
            float2 y1 = xlb[(size_t)j1 * 32 + lane];
            float2 y2 = xlb[(size_t)j2 * 32 + lane];
            float2 y3 = xlb[(size_t)j3 * 32 + lane];

            float2 q0 = leaky2(make_float2(y0.x + xr2.x, y0.y + xr2.y));
            float2 q1 = leaky2(make_float2(y1.x + xr2.x, y1.y + xr2.y));
            float2 q2 = leaky2(make_float2(y2.x + xr2.x, y2.y + xr2.y));
            float2 q3 = leaky2(make_float2(y3.x + xr2.x, y3.y + xr2.y));
            float s0 = q0.x * a2.x + q0.y * a2.y;
            float s1 = q1.x * a2.x + q1.y * a2.y;
            float s2 = q2.x * a2.x + q2.y * a2.y;
            float s3 = q3.x * a2.x + q3.y * a2.y;
#pragma unroll
            for (int o = 16; o; o >>= 1) {
                s0 += __shfl_xor_sync(0xFFFFFFFFu, s0, o);
                s1 += __shfl_xor_sync(0xFFFFFFFFu, s1, o);
                s2 += __shfl_xor_sync(0xFFFFFFFFu, s2, o);
                s3 += __shfl_xor_sync(0xFFFFFFFFu, s3, o);
            }
            float w0 = __expf(s0), w1 = __expf(s1), w2 = __expf(s2), w3 = __expf(s3);
            denom += (w0 + w1) + (w2 + w3);
            acc.x += w0 * y0.x; acc.y += w0 * y0.y;
            acc.x += w1 * y1.x; acc.y += w1 * y1.y;
            acc.x += w2 * y2.x; acc.y += w2 * y2.y;
            acc.x += w3 * y3.x; acc.y += w3 * y3.y;
        }
        for (; e < end; ++e) {
            int j = __ldg(&g_csr[e]);
            float2 y = xlb[(size_t)j * 32 + lane];
            float2 q = leaky2(make_float2(y.x + xr2.x, y.y + xr2.y));
            float s = q.x * a2.x + q.y * a2.y;
#pragma unroll
            for (int o = 16; o; o >>= 1) s += __shfl_xor_sync(0xFFFFFFFFu, s, o);
            float we = __expf(s);
            denom += we;
            acc.x += we * y.x;
            acc.y += we * y.y;
        }

        if (act) {
            float inv = 1.f / denom;
            float o0 = acc.x * inv + __ldg(&P.bo[t][2 * lane]);
            float o1 = acc.y * inv + __ldg(&P.bo[t][2 * lane + 1]);
            o0 = fmaxf(o0, 0.1f * o0);
            o1 = fmaxf(o1, 0.1f * o1);
            float2* dst = (float2*)(g_h + (size_t)i * 150 + t * 50);
            dst[lane] = make_float2(o0, o1);
        }
    }
}

// ---------------- register-tiled GEMM (round-6 verbatim) --------------------
template<int TXN, int MPT, int NT, int KDIM, int KT, int NOUT, int INSTR, int OUTSTR, bool LEAKY>
__global__ __launch_bounds__(256) void gemm_kernel(int in_sel, int out_sel,
                                                   const float* __restrict__ W,
                                                   const float* __restrict__ b) {
    const float* in = sel_buf(in_sel);
    float* out = sel_buf(out_sel);
    constexpr int NPAD = TXN * NT;
    __shared__ __align__(16) float shW[KT][NPAD];
    __shared__ float shH[64][KT + 1];
    int tid = threadIdx.x;
    int tx = tid % TXN, ty = tid / TXN;
    int node0 = blockIdx.x * 64;

    float acc[MPT][NT];
#pragma unroll
    for (int mm = 0; mm < MPT; mm++)
#pragma unroll
        for (int j = 0; j < NT; j++) acc[mm][j] = 0.f;

    for (int kt = 0; kt < KDIM; kt += KT) {
        for (int idx = tid; idx < KT * NPAD; idx += 256) {
            int k = idx / NPAD, c = idx - k * NPAD;
            shW[k][c] = (c < NOUT) ? __ldg(&W[(size_t)(kt + k) * NOUT + c]) : 0.f;
        }
        for (int idx = tid; idx < 64 * KT; idx += 256) {
            int m = idx / KT, k = idx - m * KT;
            int n = node0 + m;
            shH[m][k] = (n < NN) ? in[(size_t)n * INSTR + kt + k] : 0.f;
        }
        __syncthreads();
#pragma unroll 2
        for (int kk = 0; kk < KT; ++kk) {
            float h[MPT];
#pragma unroll
            for (int mm = 0; mm < MPT; mm++) h[mm] = shH[ty * MPT + mm][kk];
#pragma unroll
            for (int j = 0; j < NT / 2; j++) {
                float2 w2 = *reinterpret_cast<const float2*>(&shW[kk][tx * NT + 2 * j]);
#pragma unroll
                for (int mm = 0; mm < MPT; mm++) {
                    acc[mm][2 * j]     += w2.x * h[mm];
                    acc[mm][2 * j + 1] += w2.y * h[mm];
                }
            }
        }
        __syncthreads();
    }

#pragma unroll
    for (int mm = 0; mm < MPT; mm++) {
        int n = node0 + ty * MPT + mm;
        if (n >= NN) continue;
#pragma unroll
        for (int j = 0; j < NT; j++) {
            int c = tx * NT + j;
            if (c < NOUT) {
                float r = acc[mm][j] + __ldg(&b[c]);
                if (LEAKY) r = fmaxf(r, 0.1f * r);
                out[(size_t)n * OUTSTR + c] = r;
            }
        }
    }
}

// ---------------- cls2 (75->30 leaky) + cls3 (30->2) fused (round-6 verbatim)
__global__ __launch_bounds__(256) void cls23_kernel(const float* __restrict__ W2,
                                                    const float* __restrict__ b2,
                                                    const float* __restrict__ W3,
                                                    const float* __restrict__ b3,
                                                    float* __restrict__ out) {
    __shared__ float shH[64][76];
    __shared__ __align__(16) float shW[75][32];
    __shared__ float sh2[64][32];
    int tid = threadIdx.x;
    int node0 = blockIdx.x * 64;

    for (int idx = tid; idx < 75 * 32; idx += 256) {
        int k = idx >> 5, c = idx & 31;
        shW[k][c] = (c < 30) ? __ldg(&W2[k * 30 + c]) : 0.f;
    }
    for (int idx = tid; idx < 64 * 75; idx += 256) {
        int m = idx / 75, k = idx - m * 75;
        int n = node0 + m;
        shH[m][k] = (n < NN) ? g_q[(size_t)n * 80 + k] : 0.f;
    }
    __syncthreads();

    {
        int tx = tid & 15, ty = tid >> 4;
        float acc[4][2];
#pragma unroll
        for (int mm = 0; mm < 4; mm++) { acc[mm][0] = 0.f; acc[mm][1] = 0.f; }
#pragma unroll 3
        for (int k = 0; k < 75; k++) {
            float2 w2 = *reinterpret_cast<const float2*>(&shW[k][tx * 2]);
#pragma unroll
            for (int mm = 0; mm < 4; mm++) {
                float h = shH[ty * 4 + mm][k];
                acc[mm][0] += w2.x * h;
                acc[mm][1] += w2.y * h;
            }
        }
        int c = tx * 2;
        if (c < 30) {
            float bb0 = __ldg(&b2[c]), bb1 = __ldg(&b2[c + 1]);
#pragma unroll
            for (int mm = 0; mm < 4; mm++) {
                float r0 = acc[mm][0] + bb0; r0 = fmaxf(r0, 0.1f * r0);
                float r1 = acc[mm][1] + bb1; r1 = fmaxf(r1, 0.1f * r1);
                sh2[ty * 4 + mm][c] = r0;
                sh2[ty * 4 + mm][c + 1] = r1;
            }
        }
    }
    __syncthreads();

    if (tid < 128) {
        int m = tid >> 1, col = tid & 1;
        int n = node0 + m;
        if (n < NN) {
            float acc = __ldg(&b3[col]);
#pragma unroll
            for (int k = 0; k < 30; k++) acc += sh2[m][k] * __ldg(&W3[k * 2 + col]);
            out[(size_t)n * 2 + col] = acc;
        }
    }
}

// ---------------- launch ----------------------------------------------------
extern "C" void kernel_launch(void* const* d_in, const int* in_sizes, int n_in,
                              void* d_out, int out_size) {
    const float* x = (const float*)d_in[0];
    const int* ei[3] = { (const int*)d_in[1], (const int*)d_in[2], (const int*)d_in[3] };
    const float* proj_W = (const float*)d_in[22];
    const float* proj_b = (const float*)d_in[23];
    const float* W1 = (const float*)d_in[24];
    const float* b1 = (const float*)d_in[25];
    const float* W2 = (const float*)d_in[26];
    const float* b2 = (const float*)d_in[27];
    const float* W3 = (const float*)d_in[28];
    const float* b3 = (const float*)d_in[29];
    float* out = (float*)d_out;

    LinParams LP;
    AttParams AP;
    for (int t = 0; t < 3; ++t) {
        LP.Wl[t]  = (const float*)d_in[4 + 6 * t + 0];
        LP.bl[t]  = (const float*)d_in[4 + 6 * t + 1];
        LP.Wr[t]  = (const float*)d_in[4 + 6 * t + 2];
        LP.br[t]  = (const float*)d_in[4 + 6 * t + 3];
        AP.att[t] = (const float*)d_in[4 + 6 * t + 4];
        AP.bo[t]  = (const float*)d_in[4 + 6 * t + 5];
    }
    const int* s0 = ei[0], *d0 = ei[0] + EE;
    const int* s1 = ei[1], *d1 = ei[1] + EE;
    const int* s2 = ei[2], *d2 = ei[2] + EE;

    zero_cursor_kernel<<<(NN3 + 255) / 256, 256>>>();
    hist_kernel<<<2048, 256>>>(d0, d1, d2);
    scan1_kernel<<<SCAN_NB, SCAN_BS>>>();
    scan2_kernel<<<1, SCAN_BS>>>();
    scan3_kernel<<<SCAN_NB, SCAN_BS>>>();
    scatter_kernel<<<2048, 256>>>(s0, d0, s1, d1, s2, d2);

    lin_kernel<<<(NN + 31) / 32, 256>>>(x, LP);
    aggregate_kernel<<<(NN3 * 32 + 255) / 256, 256>>>(AP);

    // proj: 150 -> 150 (no act), g_h (sel 0, stride 150) -> g_p (sel 1, stride 160)
    gemm_kernel<16, 4, 10, 150, 50, 150, 150, 160, false>
        <<<(NN + 63) / 64, 256>>>(0, 1, proj_W, proj_b);
    // cls1: 150 -> 75 (leaky 0.1), g_p (sel 1, stride 160) -> g_q (sel 2, stride 80)
    gemm_kernel<8, 2, 10, 150, 50, 75, 160, 80, true>
        <<<(NN + 63) / 64, 256>>>(1, 2, W1, b1);
    // cls2 + cls3 fused
    cls23_kernel<<<(NN + 63) / 64, 256>>>(W2, b2, W3, b3, out);
}